// round 10
// baseline (speedup 1.0000x reference)
#include <cuda_runtime.h>
#include <cuda_bf16.h>
#include <cstdint>

#define DIM     64
#define KC      8192
#define NP      32768
#define GKS     256          // global row stride (elements); first 208 used
#define KCH     26           // 16B chunks per row (208 bf16)
#define MT      128          // points per CTA
#define NT      64           // codes per tile
#define NTILES  (KC / NT)    // 128
#define GT      256
#define SMLD    432          // smem row stride bytes (27*16, odd -> conflict-free)

__device__ __align__(16) __nv_bfloat16 d_A[NP * GKS];   // 16.8 MB
__device__ __align__(16) __nv_bfloat16 d_B[KC * GKS];   // 4.2 MB
__device__ float d_cn[KC];
__device__ int2  d_cand[NP];

// SMEM: A 128x432B | B 2x 64x432B
#define S_A    0
#define S_B    55296
#define BUFSZ  27648
#define SMEM_G 110592

// ---------------------------------------------------------------------------
// helpers (all generic PTX, sm_80+)
// ---------------------------------------------------------------------------
__device__ __forceinline__ uint32_t smem_u32(const void* p) {
    uint32_t a;
    asm("{ .reg .u64 t; cvta.to.shared.u64 t, %1; cvt.u32.u64 %0, t; }"
        : "=r"(a) : "l"(p));
    return a;
}
__device__ __forceinline__ void cpa16(uint32_t dst, const void* src) {
    asm volatile("cp.async.cg.shared.global [%0], [%1], 16;" :: "r"(dst), "l"(src)
                 : "memory");
}
#define CP_COMMIT() asm volatile("cp.async.commit_group;" ::: "memory")
#define CP_WAIT1()  asm volatile("cp.async.wait_group 1;" ::: "memory")

__device__ __forceinline__ void ldm_x4(uint32_t* r, uint32_t addr) {
    asm volatile("ldmatrix.sync.aligned.m8n8.x4.shared.b16 {%0,%1,%2,%3}, [%4];"
                 : "=r"(r[0]), "=r"(r[1]), "=r"(r[2]), "=r"(r[3]) : "r"(addr));
}
__device__ __forceinline__ void mma_bf16(float* d, const uint32_t* a,
                                         uint32_t b0, uint32_t b1) {
    asm volatile(
        "mma.sync.aligned.m16n8k16.row.col.f32.bf16.bf16.f32 "
        "{%0,%1,%2,%3}, {%4,%5,%6,%7}, {%8,%9}, {%0,%1,%2,%3};"
        : "+f"(d[0]), "+f"(d[1]), "+f"(d[2]), "+f"(d[3])
        : "r"(a[0]), "r"(a[1]), "r"(a[2]), "r"(a[3]), "r"(b0), "r"(b1));
}

// ---------------------------------------------------------------------------
// prep kernels
// ---------------------------------------------------------------------------
// nc_k (exact, reference rounding) + write B correction block [nch, ncl, 0..]
__global__ void __launch_bounds__(256) prep_cn(const float* __restrict__ cb) {
    int k = blockIdx.x * 256 + threadIdx.x;
    const float* row = cb + (size_t)k * DIM;
    float s = 0.f;
#pragma unroll
    for (int i = 0; i < DIM; i++)
        s = __fadd_rn(s, __fmul_rn(row[i], row[i]));
    d_cn[k] = s;
    float nc2 = -0.5f * s;                       // exact scale by 0.5
    __nv_bfloat16 bh = __float2bfloat16(nc2);
    __nv_bfloat16 bl = __float2bfloat16(nc2 - __bfloat162float(bh));
    uint32_t* br = (uint32_t*)d_B + (size_t)k * (GKS / 2);
    br[96] = (uint32_t)__bfloat16_as_ushort(bh) |
             ((uint32_t)__bfloat16_as_ushort(bl) << 16);
#pragma unroll
    for (int c = 97; c < 104; c++) br[c] = 0u;
}

// A' rows: [hi(64) | lo(64) | hi(64) | 1,1,0.. (16)]
__global__ void __launch_bounds__(128) prep_A(const float* __restrict__ ze) {
    __shared__ float xs[DIM * 64];
    const int tid = threadIdx.x;
    const int n0  = blockIdx.x * 64;
    const int b   = n0 >> 12;
    const int hw0 = n0 & 4095;
    const float* zb = ze + (size_t)b * DIM * 4096 + hw0;
#pragma unroll
    for (int it = 0; it < 32; it++) {
        int e = tid + it * 128;
        int nl = e & 63, d = e >> 6;
        xs[d * 64 + nl] = zb[(size_t)d * 4096 + nl];
    }
    __syncthreads();
    uint32_t* out = (uint32_t*)d_A;
#pragma unroll
    for (int i = 0; i < 52; i++) {
        int e   = tid + i * 128;      // 0..6655
        int nl  = e / 104;
        int c   = e % 104;            // uint col (2 bf16)
        uint32_t u;
        if (c < 96) {
            int blk = c >> 5;         // 0:hi 1:lo 2:hi
            int d0  = (c & 31) * 2;
            float v0 = xs[d0 * 64 + nl], v1 = xs[(d0 + 1) * 64 + nl];
            __nv_bfloat16 h0 = __float2bfloat16(v0);
            __nv_bfloat16 h1 = __float2bfloat16(v1);
            if (blk == 1) {
                h0 = __float2bfloat16(v0 - __bfloat162float(h0));
                h1 = __float2bfloat16(v1 - __bfloat162float(h1));
            }
            u = (uint32_t)__bfloat16_as_ushort(h0) |
                ((uint32_t)__bfloat16_as_ushort(h1) << 16);
        } else {
            u = (c == 96) ? 0x3F803F80u : 0u;    // (1.0, 1.0) bf16 pair
        }
        out[(size_t)(n0 + nl) * (GKS / 2) + c] = u;
    }
}

// B' rows: [hi | hi | lo] (correction block written by prep_cn)
__global__ void __launch_bounds__(256) prep_B(const float* __restrict__ cb) {
    int idx = blockIdx.x * 256 + threadIdx.x;   // 0 .. 8192*96-1
    int row = idx / 96;
    int c   = idx % 96;
    int blk = c >> 5;                 // 0:hi 1:hi 2:lo
    int d0  = (c & 31) * 2;
    float v0 = cb[(size_t)row * 64 + d0], v1 = cb[(size_t)row * 64 + d0 + 1];
    __nv_bfloat16 h0 = __float2bfloat16(v0);
    __nv_bfloat16 h1 = __float2bfloat16(v1);
    if (blk == 2) {
        h0 = __float2bfloat16(v0 - __bfloat162float(h0));
        h1 = __float2bfloat16(v1 - __bfloat162float(h1));
    }
    ((uint32_t*)d_B)[(size_t)row * (GKS / 2) + c] =
        (uint32_t)__bfloat16_as_ushort(h0) | ((uint32_t)__bfloat16_as_ushort(h1) << 16);
}

// ---------------------------------------------------------------------------
// GEMM (mma.sync bf16, nc folded in) + pair-max top-2 epilogue
// ---------------------------------------------------------------------------
__global__ void __launch_bounds__(GT, 2) gemm_kernel() {
    extern __shared__ char smem[];
    const uint32_t sb = smem_u32(smem);
    const int tid = threadIdx.x;
    const int wid = tid >> 5;
    const int l   = tid & 31;
    const int wm  = wid & 3;          // M-warp 0..3 (32 rows each)
    const int wn  = wid >> 2;         // N-warp 0..1 (32 cols each)
    const int m0  = blockIdx.x * MT;

    // precompute B-fill addressing (row = e/26, chunk = e%26); 1664 chunks
    uint32_t bDst[7];
    int      bSrc[7];
    int      bValid[7];
#pragma unroll
    for (int i = 0; i < 7; i++) {
        int e = tid + GT * i;
        int row = e / KCH, c = e - row * KCH;
        bValid[i] = (e < NT * KCH);
        bDst[i] = sb + S_B + (uint32_t)(row * SMLD + c * 16);
        bSrc[i] = row * GKS + c * 8;
    }

    // A tile (once)
#pragma unroll
    for (int i = 0; i < 13; i++) {
        int e = tid + GT * i;         // 0..3327
        int row = e / KCH, c = e - row * KCH;
        cpa16(sb + S_A + row * SMLD + c * 16,
              d_A + (size_t)(m0 + row) * GKS + c * 8);
    }
    // B tiles 0 and 1
#pragma unroll
    for (int i = 0; i < 7; i++)
        if (bValid[i]) cpa16(bDst[i], d_B + bSrc[i]);
    CP_COMMIT();
#pragma unroll
    for (int i = 0; i < 7; i++)
        if (bValid[i]) cpa16(bDst[i] + BUFSZ, d_B + NT * GKS + bSrc[i]);
    CP_COMMIT();
    CP_WAIT1();
    __syncthreads();                  // A + B0 ready

    // ldmatrix per-thread base addresses
    const uint32_t aA0 = sb + S_A + (wm * 32 + (l & 15)) * SMLD + (l >> 4) * 16;
    const uint32_t aA1 = aA0 + 16 * SMLD;
    const uint32_t bRow = (uint32_t)(wn * 32 + (l & 7) + ((l >> 3) & 1) * 8);
    const uint32_t aB0 = sb + S_B + bRow * SMLD + (l >> 4) * 16;
    const uint32_t aB1 = aB0 + 16 * SMLD;

    const int pb0 = wn * 16 + (l & 3);   // pair-id base within tile

    // 8 trackers of top-2 MAX (m'' = m - nc/2), storing pair ids
    float b1[8], b2[8];
    int   i1[8], i2[8];
#pragma unroll
    for (int s = 0; s < 8; s++) { b1[s] = -3.4e38f; b2[s] = -3.4e38f; i1[s] = 0; i2[s] = 0; }

#pragma unroll 1
    for (int t = 0; t < NTILES; t++) {
        const int buf = t & 1;
        const uint32_t boff = (uint32_t)buf * BUFSZ;

        float acc[2][4][4];
#pragma unroll
        for (int mt = 0; mt < 2; mt++)
#pragma unroll
            for (int j = 0; j < 4; j++)
#pragma unroll
                for (int q = 0; q < 4; q++) acc[mt][j][q] = 0.f;

#pragma unroll
        for (int ks = 0; ks < 13; ks++) {
            const uint32_t koff = (uint32_t)(ks * 32);   // 16 bf16 = 32 B
            uint32_t ra0[4], ra1[4], rb01[4], rb23[4];
            ldm_x4(ra0,  aA0 + koff);
            ldm_x4(ra1,  aA1 + koff);
            ldm_x4(rb01, aB0 + boff + koff);
            ldm_x4(rb23, aB1 + boff + koff);
            mma_bf16(acc[0][0], ra0, rb01[0], rb01[2]);
            mma_bf16(acc[0][1], ra0, rb01[1], rb01[3]);
            mma_bf16(acc[0][2], ra0, rb23[0], rb23[2]);
            mma_bf16(acc[0][3], ra0, rb23[1], rb23[3]);
            mma_bf16(acc[1][0], ra1, rb01[0], rb01[2]);
            mma_bf16(acc[1][1], ra1, rb01[1], rb01[3]);
            mma_bf16(acc[1][2], ra1, rb23[0], rb23[2]);
            mma_bf16(acc[1][3], ra1, rb23[1], rb23[3]);
        }

        // epilogue: pair-max + top-2 insert (8 independent chains, depth 2)
        const int pb = t * 32 + pb0;
#pragma unroll
        for (int j = 0; j < 4; j++) {
            const int pid = pb + j * 4;
            const int par = j & 1;
#pragma unroll
            for (int mt = 0; mt < 2; mt++) {
                const int s0 = (mt * 2) * 2 + par;
                const int s1 = (mt * 2 + 1) * 2 + par;
                float p0 = fmaxf(acc[mt][j][0], acc[mt][j][1]);
                float p1 = fmaxf(acc[mt][j][2], acc[mt][j][3]);
                if (p0 > b1[s0]) { b2[s0] = b1[s0]; i2[s0] = i1[s0]; b1[s0] = p0; i1[s0] = pid; }
                else if (p0 > b2[s0]) { b2[s0] = p0; i2[s0] = pid; }
                if (p1 > b1[s1]) { b2[s1] = b1[s1]; i2[s1] = i1[s1]; b1[s1] = p1; i1[s1] = pid; }
                else if (p1 > b2[s1]) { b2[s1] = p1; i2[s1] = pid; }
            }
        }

        __syncthreads();                       // everyone done reading buf
        if (t + 2 < NTILES) {
            const __nv_bfloat16* src = d_B + (size_t)(t + 2) * NT * GKS;
#pragma unroll
            for (int i = 0; i < 7; i++)
                if (bValid[i]) cpa16(bDst[i] + boff, src + bSrc[i]);
        }
        CP_COMMIT();
        CP_WAIT1();                            // B(t+1) ready
        __syncthreads();
    }

    // merge tracker pairs (even/odd j) -> 4 row slots
    float m1[4], m2[4];
    int   n1[4], n2i[4];
#pragma unroll
    for (int s = 0; s < 4; s++) {
        float a1 = b1[2 * s], a2 = b2[2 * s];
        int   x1 = i1[2 * s], x2 = i2[2 * s];
        float c1v = b1[2 * s + 1], c2v = b2[2 * s + 1];
        int   y1 = i1[2 * s + 1], y2 = i2[2 * s + 1];
        if (c1v > a1) {
            float t2v = fmaxf(a1, c2v);
            int   t2i = (c2v > a1) ? y2 : x1;
            a2 = t2v; x2 = t2i;
            a1 = c1v; x1 = y1;
        } else if (c1v > a2) {
            a2 = c1v; x2 = y1;
        }
        m1[s] = a1; n1[s] = x1; m2[s] = a2; n2i[s] = x2;
    }

    // quad merge (lanes sharing l>>2 hold same rows)
#pragma unroll
    for (int s = 0; s < 4; s++) {
#pragma unroll
        for (int off = 1; off <= 2; off <<= 1) {
            float t1 = __shfl_xor_sync(0xFFFFFFFFu, m1[s], off);
            int   j1 = __shfl_xor_sync(0xFFFFFFFFu, n1[s], off);
            float t2 = __shfl_xor_sync(0xFFFFFFFFu, m2[s], off);
            int   j2 = __shfl_xor_sync(0xFFFFFFFFu, n2i[s], off);
            if (t1 > m1[s]) {
                float nb2 = fmaxf(m1[s], t2);
                int   ni2 = (t2 > m1[s]) ? j2 : n1[s];
                m1[s] = t1; n1[s] = j1; m2[s] = nb2; n2i[s] = ni2;
            } else if (t1 > m2[s]) {
                m2[s] = t1; n2i[s] = j1;
            }
        }
    }

    // cross-N-warp merge via smem (reuse B region)
    float4* red = (float4*)(smem + S_B);       // [128 rows][2 wn]
    if ((l & 3) == 0) {
#pragma unroll
        for (int s = 0; s < 4; s++) {
            int row = wm * 32 + (s >> 1) * 16 + (s & 1) * 8 + (l >> 2);
            red[row * 2 + wn] = make_float4(m1[s], __int_as_float(n1[s]),
                                            m2[s], __int_as_float(n2i[s]));
        }
    }
    __syncthreads();
    if (tid < MT) {
        float4 A4 = red[tid * 2 + 0];
        float4 B4 = red[tid * 2 + 1];
        float s1 = A4.x, s2 = A4.z;
        int   k1 = __float_as_int(A4.y), k2 = __float_as_int(A4.w);
        float t1 = B4.x, t2 = B4.z;
        int   j1 = __float_as_int(B4.y), j2 = __float_as_int(B4.w);
        if (t1 > s1) {
            float n2v = fmaxf(s1, t2);
            int   n2x = (t2 > s1) ? j2 : k1;
            s1 = t1; k1 = j1; s2 = n2v; k2 = n2x;
        } else if (t1 > s2) {
            s2 = t1; k2 = j1;
        }
        d_cand[m0 + tid] = make_int2(k1, k2);   // two PAIR ids
    }
}

// ---------------------------------------------------------------------------
// finalize: exact rescore of 4 candidates (reference rounding) + gather
// ---------------------------------------------------------------------------
__global__ void __launch_bounds__(128) finalize(const float* __restrict__ ze,
                                                const float* __restrict__ cb,
                                                float* __restrict__ out) {
    __shared__ int bx[64];
    const int tid = threadIdx.x;
    const int n0  = blockIdx.x * 64;
    const int b   = n0 >> 12;
    const int hw0 = n0 & 4095;

    if (tid < 64) {
        const int n  = n0 + tid;
        const int hw = hw0 + tid;
        float x[DIM];
#pragma unroll
        for (int d = 0; d < DIM; d++)
            x[d] = ze[(size_t)(b * DIM + d) * 4096 + hw];
        float nx = 0.f;
#pragma unroll
        for (int d = 0; d < DIM; d++)
            nx = __fadd_rn(nx, __fmul_rn(x[d], x[d]));
        int2 cd = d_cand[n];
        int pa = min(cd.x, cd.y), pb = max(cd.x, cd.y);
        int cands[4] = {2 * pa, 2 * pa + 1, 2 * pb, 2 * pb + 1};  // ascending
        float bd = 3.4e38f;
        int   bi = 0;
#pragma unroll
        for (int q = 0; q < 4; q++) {
            int k = cands[q];
            const float* r = cb + (size_t)k * DIM;
            float m = 0.f;
#pragma unroll
            for (int d = 0; d < DIM; d++)
                m = __fmaf_rn(x[d], r[d], m);
            float d2 = __fadd_rn(__fadd_rn(nx, -__fmul_rn(2.0f, m)), d_cn[k]);
            if (d2 < bd) { bd = d2; bi = k; }   // strict: tie -> lower index
        }
        bx[tid] = bi;
    }
    __syncthreads();

    float* ob = out + (size_t)b * DIM * 4096 + hw0;
#pragma unroll
    for (int it = 0; it < 32; it++) {
        int e = tid + it * 128;
        int nl = e & 63, d = e >> 6;
        ob[(size_t)d * 4096 + nl] = cb[(size_t)bx[nl] * DIM + d];
    }
}

extern "C" void kernel_launch(void* const* d_in, const int* in_sizes, int n_in,
                              void* d_out, int out_size) {
    const float* ze = (const float*)d_in[0];   // [8,64,64,64] f32
    const float* cb = (const float*)d_in[1];   // [8192,64] f32
    float* out = (float*)d_out;

    cudaFuncSetAttribute(gemm_kernel, cudaFuncAttributeMaxDynamicSharedMemorySize,
                         SMEM_G);

    prep_cn<<<KC / 256, 256>>>(cb);
    prep_A<<<NP / 64, 128>>>(ze);
    prep_B<<<(KC * 96) / 256, 256>>>(cb);
    gemm_kernel<<<NP / MT, GT, SMEM_G>>>();
    finalize<<<NP / 64, 128>>>(ze, cb, out);
}

// round 11
// speedup vs baseline: 1.1170x; 1.1170x over previous
#include <cuda_runtime.h>
#include <cuda_bf16.h>
#include <cstdint>

#define DIM     64
#define KC      8192
#define NP      32768
#define MT      128          // points per CTA
#define NT      64           // codes per tile
#define NTILES  (KC / NT)    // 128
#define GT      256
#define SMLD    400          // row stride bytes (25*16, odd -> conflict-free ldsm)

// A: [256 blocks][128 rows][200 bf16] contiguous (pad cols 192..199 zero)
__device__ __align__(16) __nv_bfloat16 d_A2[NP * 200];   // 13.1 MB
// B: [128 tiles][64 rows][200 bf16] contiguous
__device__ __align__(16) __nv_bfloat16 d_B2[KC * 200];   // 3.3 MB
__device__ __align__(16) float d_cn[KC];
__device__ int2  d_cand[NP];

// SMEM: A 128x400 | B 2x 64x400 | cn 2x 256B | mbar 2x8
#define S_A    0
#define S_B    51200
#define BUFSZ  25600
#define S_CN   102400
#define S_MB   102912
#define SMEM_G 102944

// ---------------------------------------------------------------------------
// helpers (all generic PTX, sm_90)
// ---------------------------------------------------------------------------
__device__ __forceinline__ uint32_t smem_u32(const void* p) {
    uint32_t a;
    asm("{ .reg .u64 t; cvta.to.shared.u64 t, %1; cvt.u32.u64 %0, t; }"
        : "=r"(a) : "l"(p));
    return a;
}
__device__ __forceinline__ void bulkcp(uint32_t dst, const void* src,
                                       uint32_t bytes, uint32_t mbar) {
    asm volatile(
        "cp.async.bulk.shared::cluster.global.mbarrier::complete_tx::bytes "
        "[%0], [%1], %2, [%3];"
        :: "r"(dst), "l"(src), "r"(bytes), "r"(mbar) : "memory");
}
#define MBAR_INIT(a, n) \
    asm volatile("mbarrier.init.shared.b64 [%0], %1;" :: "r"(a), "r"(n) : "memory")
#define MBAR_EXPECT(a, bytes) \
    asm volatile("mbarrier.arrive.expect_tx.shared.b64 _, [%0], %1;" \
                 :: "r"(a), "r"(bytes) : "memory")
__device__ __forceinline__ void mbar_wait(uint32_t mbar, uint32_t parity) {
    asm volatile(
        "{\n\t.reg .pred P;\n\t"
        "WL_%=:\n\t"
        "mbarrier.try_wait.parity.acquire.cta.shared::cta.b64 P, [%0], %1, 0x989680;\n\t"
        "@P bra.uni WD_%=;\n\t"
        "bra.uni WL_%=;\n\t"
        "WD_%=:\n\t}"
        :: "r"(mbar), "r"(parity) : "memory");
}
__device__ __forceinline__ void ldm_x4(uint32_t* r, uint32_t addr) {
    asm volatile("ldmatrix.sync.aligned.m8n8.x4.shared.b16 {%0,%1,%2,%3}, [%4];"
                 : "=r"(r[0]), "=r"(r[1]), "=r"(r[2]), "=r"(r[3]) : "r"(addr));
}
__device__ __forceinline__ void mma_bf16(float* d, const uint32_t* a,
                                         uint32_t b0, uint32_t b1) {
    asm volatile(
        "mma.sync.aligned.m16n8k16.row.col.f32.bf16.bf16.f32 "
        "{%0,%1,%2,%3}, {%4,%5,%6,%7}, {%8,%9}, {%0,%1,%2,%3};"
        : "+f"(d[0]), "+f"(d[1]), "+f"(d[2]), "+f"(d[3])
        : "r"(a[0]), "r"(a[1]), "r"(a[2]), "r"(a[3]), "r"(b0), "r"(b1));
}

// ---------------------------------------------------------------------------
// prep kernels
// ---------------------------------------------------------------------------
__global__ void __launch_bounds__(256) prep_cn(const float* __restrict__ cb) {
    int k = blockIdx.x * 256 + threadIdx.x;
    const float* row = cb + (size_t)k * DIM;
    float s = 0.f;
#pragma unroll
    for (int i = 0; i < DIM; i++)
        s = __fadd_rn(s, __fmul_rn(row[i], row[i]));
    d_cn[k] = s;
}

// A' rows: [hi(64) | lo(64) | hi(64) | pad(8)] into contiguous 400B-stride blocks
__global__ void __launch_bounds__(256) prep_A(const float* __restrict__ ze) {
    __shared__ float xs[DIM * 128];
    const int tid = threadIdx.x;
    const int n0  = blockIdx.x * 128;
    const int b   = n0 >> 12;
    const int hw0 = n0 & 4095;
    const float* zb = ze + (size_t)b * DIM * 4096 + hw0;
#pragma unroll
    for (int it = 0; it < 32; it++) {
        int e = tid + it * 256;
        int nl = e & 127, d = e >> 7;
        xs[d * 128 + nl] = zb[(size_t)d * 4096 + nl];
    }
    __syncthreads();
    uint32_t* out = (uint32_t*)d_A2 + (size_t)blockIdx.x * 12800;
#pragma unroll
    for (int i = 0; i < 50; i++) {
        int e   = tid + i * 256;      // 0..12799
        int row = e / 100;
        int c   = e % 100;            // uint col (2 bf16)
        uint32_t u = 0u;
        if (c < 96) {
            int blk = c >> 5;         // 0:hi 1:lo 2:hi
            int d0  = (c & 31) * 2;
            float v0 = xs[d0 * 128 + row], v1 = xs[(d0 + 1) * 128 + row];
            __nv_bfloat16 h0 = __float2bfloat16(v0);
            __nv_bfloat16 h1 = __float2bfloat16(v1);
            if (blk == 1) {
                h0 = __float2bfloat16(v0 - __bfloat162float(h0));
                h1 = __float2bfloat16(v1 - __bfloat162float(h1));
            }
            u = (uint32_t)__bfloat16_as_ushort(h0) |
                ((uint32_t)__bfloat16_as_ushort(h1) << 16);
        }
        out[row * 100 + c] = u;
    }
}

// B' rows: [hi | hi | lo | pad(8)] into contiguous 400B-stride tile blocks
__global__ void __launch_bounds__(256) prep_B(const float* __restrict__ cb) {
    int idx = blockIdx.x * 256 + threadIdx.x;   // 0 .. 8192*100-1
    int row = idx / 100;
    int c   = idx % 100;
    uint32_t u = 0u;
    if (c < 96) {
        int blk = c >> 5;             // 0:hi 1:hi 2:lo
        int d0  = (c & 31) * 2;
        float v0 = cb[(size_t)row * 64 + d0], v1 = cb[(size_t)row * 64 + d0 + 1];
        __nv_bfloat16 h0 = __float2bfloat16(v0);
        __nv_bfloat16 h1 = __float2bfloat16(v1);
        if (blk == 2) {
            h0 = __float2bfloat16(v0 - __bfloat162float(h0));
            h1 = __float2bfloat16(v1 - __bfloat162float(h1));
        }
        u = (uint32_t)__bfloat16_as_ushort(h0) |
            ((uint32_t)__bfloat16_as_ushort(h1) << 16);
    }
    ((uint32_t*)d_B2)[(size_t)row * 100 + c] = u;
}

// ---------------------------------------------------------------------------
// GEMM (mma.sync bf16) + top-2 epilogue; B staged via cp.async.bulk + mbarrier
// ---------------------------------------------------------------------------
__global__ void __launch_bounds__(GT, 2) gemm_kernel() {
    extern __shared__ char smem[];
    const uint32_t sb = smem_u32(smem);
    const int tid = threadIdx.x;
    const int wid = tid >> 5;
    const int l   = tid & 31;
    const int wm  = wid & 3;          // M-warp 0..3 (32 rows each)
    const int wn  = wid >> 2;         // N-warp 0..1 (32 cols each)
    const int m0  = blockIdx.x * MT;

    if (tid == 0) {
        MBAR_INIT(sb + S_MB, 1);
        MBAR_INIT(sb + S_MB + 8, 1);
    }
    __syncthreads();
    if (tid == 0) {
        // stage 0: A + B0 + cn0
        MBAR_EXPECT(sb + S_MB, 51200u + 25600u + 256u);
        bulkcp(sb + S_A, (const char*)d_A2 + (size_t)blockIdx.x * 51200, 51200u,
               sb + S_MB);
        bulkcp(sb + S_B, (const char*)d_B2, 25600u, sb + S_MB);
        bulkcp(sb + S_CN, (const char*)d_cn, 256u, sb + S_MB);
        // stage 1: B1 + cn1
        MBAR_EXPECT(sb + S_MB + 8, 25856u);
        bulkcp(sb + S_B + BUFSZ, (const char*)d_B2 + 25600, 25600u, sb + S_MB + 8);
        bulkcp(sb + S_CN + 256, (const char*)d_cn + 256, 256u, sb + S_MB + 8);
    }

    // ldmatrix per-thread base addresses
    const uint32_t aA0 = sb + S_A + (wm * 32 + (l & 15)) * SMLD + (l >> 4) * 16;
    const uint32_t aA1 = aA0 + 16 * SMLD;
    const uint32_t bRow = (uint32_t)(wn * 32 + (l & 7) + ((l >> 3) & 1) * 8);
    const uint32_t aB0 = sb + S_B + bRow * SMLD + (l >> 4) * 16;
    const uint32_t aB1 = aB0 + 16 * SMLD;

    const int cb0 = wn * 32 + 2 * (l & 3);   // epilogue column base

    // 8 trackers: index = row-slot (mt*2+half)*2 + (j&1)
    float b1[8], b2[8];
    int   i1[8], i2[8];
#pragma unroll
    for (int s = 0; s < 8; s++) { b1[s] = 3.4e38f; b2[s] = 3.4e38f; i1[s] = 0; i2[s] = 0; }

#pragma unroll 1
    for (int t = 0; t < NTILES; t++) {
        const int buf = t & 1;
        const uint32_t boff = (uint32_t)buf * BUFSZ;
        mbar_wait(sb + S_MB + 8 * buf, (t >> 1) & 1);

        float acc[2][4][4];
#pragma unroll
        for (int mt = 0; mt < 2; mt++)
#pragma unroll
            for (int j = 0; j < 4; j++)
#pragma unroll
                for (int q = 0; q < 4; q++) acc[mt][j][q] = 0.f;

#pragma unroll
        for (int ks = 0; ks < 12; ks++) {
            const uint32_t koff = (uint32_t)(ks * 32);   // 16 bf16 = 32 B
            uint32_t ra0[4], ra1[4], rb01[4], rb23[4];
            ldm_x4(ra0,  aA0 + koff);
            ldm_x4(ra1,  aA1 + koff);
            ldm_x4(rb01, aB0 + boff + koff);
            ldm_x4(rb23, aB1 + boff + koff);
            mma_bf16(acc[0][0], ra0, rb01[0], rb01[2]);
            mma_bf16(acc[0][1], ra0, rb01[1], rb01[3]);
            mma_bf16(acc[0][2], ra0, rb23[0], rb23[2]);
            mma_bf16(acc[0][3], ra0, rb23[1], rb23[3]);
            mma_bf16(acc[1][0], ra1, rb01[0], rb01[2]);
            mma_bf16(acc[1][1], ra1, rb01[1], rb01[3]);
            mma_bf16(acc[1][2], ra1, rb23[0], rb23[2]);
            mma_bf16(acc[1][3], ra1, rb23[1], rb23[3]);
        }

        // hoist cn slice into regs (buffer is overwritten by t+2 copy)
        const float* cnp = (const float*)(smem + S_CN + buf * 256);
        float creg[8];
#pragma unroll
        for (int j = 0; j < 4; j++) {
            creg[2 * j]     = cnp[cb0 + j * 8];
            creg[2 * j + 1] = cnp[cb0 + j * 8 + 1];
        }

        __syncthreads();                       // all warps done with buf
        if (tid == 0 && t + 2 < NTILES) {
            uint32_t mb = sb + S_MB + 8 * buf;
            MBAR_EXPECT(mb, 25856u);
            bulkcp(sb + S_B + boff, (const char*)d_B2 + (size_t)(t + 2) * 25600,
                   25600u, mb);
            bulkcp(sb + S_CN + buf * 256, (const char*)d_cn + (size_t)(t + 2) * 256,
                   256u, mb);
        }

        // epilogue: score = nc - 2*m; 8 independent top-2 chains
        const int kb0 = t * NT + cb0;
#pragma unroll
        for (int j = 0; j < 4; j++) {
            float c0 = creg[2 * j];
            float c1 = creg[2 * j + 1];
            int kk = kb0 + j * 8;
            const int par = j & 1;
#pragma unroll
            for (int mt = 0; mt < 2; mt++) {
                const int s0 = (mt * 2) * 2 + par;
                const int s1 = (mt * 2 + 1) * 2 + par;
                float v0 = fmaf(-2.f, acc[mt][j][0], c0);
                float v1 = fmaf(-2.f, acc[mt][j][1], c1);
                float v2 = fmaf(-2.f, acc[mt][j][2], c0);
                float v3 = fmaf(-2.f, acc[mt][j][3], c1);
                if (v0 < b1[s0]) { b2[s0] = b1[s0]; i2[s0] = i1[s0]; b1[s0] = v0; i1[s0] = kk; }
                else if (v0 < b2[s0]) { b2[s0] = v0; i2[s0] = kk; }
                if (v1 < b1[s0]) { b2[s0] = b1[s0]; i2[s0] = i1[s0]; b1[s0] = v1; i1[s0] = kk + 1; }
                else if (v1 < b2[s0]) { b2[s0] = v1; i2[s0] = kk + 1; }
                if (v2 < b1[s1]) { b2[s1] = b1[s1]; i2[s1] = i1[s1]; b1[s1] = v2; i1[s1] = kk; }
                else if (v2 < b2[s1]) { b2[s1] = v2; i2[s1] = kk; }
                if (v3 < b1[s1]) { b2[s1] = b1[s1]; i2[s1] = i1[s1]; b1[s1] = v3; i1[s1] = kk + 1; }
                else if (v3 < b2[s1]) { b2[s1] = v3; i2[s1] = kk + 1; }
            }
        }
    }

    // merge tracker pairs (even/odd j) -> 4 row slots
    float m1[4], m2[4];
    int   n1[4], n2i[4];
#pragma unroll
    for (int s = 0; s < 4; s++) {
        float a1 = b1[2 * s], a2 = b2[2 * s];
        int   x1 = i1[2 * s], x2 = i2[2 * s];
        float c1v = b1[2 * s + 1], c2v = b2[2 * s + 1];
        int   y1 = i1[2 * s + 1], y2 = i2[2 * s + 1];
        if (c1v < a1) {
            float t2v = fminf(a1, c2v);
            int   t2i = (c2v < a1) ? y2 : x1;
            a2 = t2v; x2 = t2i;
            a1 = c1v; x1 = y1;
        } else if (c1v < a2) {
            a2 = c1v; x2 = y1;
        }
        m1[s] = a1; n1[s] = x1; m2[s] = a2; n2i[s] = x2;
    }

    // quad merge (lanes sharing l>>2 hold same rows)
#pragma unroll
    for (int s = 0; s < 4; s++) {
#pragma unroll
        for (int off = 1; off <= 2; off <<= 1) {
            float t1 = __shfl_xor_sync(0xFFFFFFFFu, m1[s], off);
            int   j1 = __shfl_xor_sync(0xFFFFFFFFu, n1[s], off);
            float t2 = __shfl_xor_sync(0xFFFFFFFFu, m2[s], off);
            int   j2 = __shfl_xor_sync(0xFFFFFFFFu, n2i[s], off);
            if (t1 < m1[s]) {
                float nb2 = fminf(m1[s], t2);
                int   ni2 = (t2 < m1[s]) ? j2 : n1[s];
                m1[s] = t1; n1[s] = j1; m2[s] = nb2; n2i[s] = ni2;
            } else if (t1 < m2[s]) {
                m2[s] = t1; n2i[s] = j1;
            }
        }
    }

    // cross-N-warp merge via smem (reuse B region; all B reads done pre-sync)
    float4* red = (float4*)(smem + S_B);       // [128 rows][2 wn]
    if ((l & 3) == 0) {
#pragma unroll
        for (int s = 0; s < 4; s++) {
            int row = wm * 32 + (s >> 1) * 16 + (s & 1) * 8 + (l >> 2);
            red[row * 2 + wn] = make_float4(m1[s], __int_as_float(n1[s]),
                                            m2[s], __int_as_float(n2i[s]));
        }
    }
    __syncthreads();
    if (tid < MT) {
        float4 A4 = red[tid * 2 + 0];
        float4 B4 = red[tid * 2 + 1];
        float s1 = A4.x, s2 = A4.z;
        int   k1 = __float_as_int(A4.y), k2 = __float_as_int(A4.w);
        float t1 = B4.x, t2 = B4.z;
        int   j1 = __float_as_int(B4.y), j2 = __float_as_int(B4.w);
        if (t1 < s1) {
            float n2v = fminf(s1, t2);
            int   n2x = (t2 < s1) ? j2 : k1;
            s1 = t1; k1 = j1; s2 = n2v; k2 = n2x;
        } else if (t1 < s2) {
            s2 = t1; k2 = j1;
        }
        d_cand[m0 + tid] = make_int2(k1, k2);
    }
}

// ---------------------------------------------------------------------------
// finalize: exact rescore (reference-identical rounding) + gather, fused.
// ---------------------------------------------------------------------------
__global__ void __launch_bounds__(128) finalize(const float* __restrict__ ze,
                                                const float* __restrict__ cb,
                                                float* __restrict__ out) {
    __shared__ int bx[64];
    const int tid = threadIdx.x;
    const int n0  = blockIdx.x * 64;
    const int b   = n0 >> 12;
    const int hw0 = n0 & 4095;

    if (tid < 64) {
        const int n  = n0 + tid;
        const int hw = hw0 + tid;
        float x[DIM];
#pragma unroll
        for (int d = 0; d < DIM; d++)
            x[d] = ze[(size_t)(b * DIM + d) * 4096 + hw];
        float nx = 0.f;
#pragma unroll
        for (int d = 0; d < DIM; d++)
            nx = __fadd_rn(nx, __fmul_rn(x[d], x[d]));
        int2 cd = d_cand[n];
        int ka = min(cd.x, cd.y), kb = max(cd.x, cd.y);
        const float* ra = cb + (size_t)ka * DIM;
        const float* rb = cb + (size_t)kb * DIM;
        float ma = 0.f, mb = 0.f;
#pragma unroll
        for (int d = 0; d < DIM; d++) {
            ma = __fmaf_rn(x[d], ra[d], ma);
            mb = __fmaf_rn(x[d], rb[d], mb);
        }
        float d2a = __fadd_rn(__fadd_rn(nx, -__fmul_rn(2.0f, ma)), d_cn[ka]);
        float d2b = __fadd_rn(__fadd_rn(nx, -__fmul_rn(2.0f, mb)), d_cn[kb]);
        bx[tid] = (d2b < d2a) ? kb : ka;   // strict: tie -> lower index
    }
    __syncthreads();

    float* ob = out + (size_t)b * DIM * 4096 + hw0;
#pragma unroll
    for (int it = 0; it < 32; it++) {
        int e = tid + it * 128;
        int nl = e & 63, d = e >> 6;
        ob[(size_t)d * 4096 + nl] = cb[(size_t)bx[nl] * DIM + d];
    }
}

extern "C" void kernel_launch(void* const* d_in, const int* in_sizes, int n_in,
                              void* d_out, int out_size) {
    const float* ze = (const float*)d_in[0];   // [8,64,64,64] f32
    const float* cb = (const float*)d_in[1];   // [8192,64] f32
    float* out = (float*)d_out;

    cudaFuncSetAttribute(gemm_kernel, cudaFuncAttributeMaxDynamicSharedMemorySize,
                         SMEM_G);

    prep_cn<<<KC / 256, 256>>>(cb);
    prep_A<<<NP / 128, 256>>>(ze);
    prep_B<<<(KC * 100) / 256, 256>>>(cb);
    gemm_kernel<<<NP / MT, GT, SMEM_G>>>();
    finalize<<<NP / 64, 128>>>(ze, cb, out);
}